// round 8
// baseline (speedup 1.0000x reference)
#include <cuda_runtime.h>
#include <math.h>
#include <stdint.h>

// NT-Xent loss. N=8192 rows (interleaved zjs/zis), D=256.
// score = 2*cos in [-2,2] -> fixed-shift LSE:
//   loss_i = 2 + ln(sum_{j!=i} exp(2 d_ij - 2)) - 2 d_{i, i^1}
// int8 IMMA, persistent-band CTAs: A resident in smem, B streamed.
// 160 CTAs = 32 band-pairs x 5 splits, 13 tiles each (exact cover of the
// 2080-tile upper triangle). Row exp-sums accumulate in registers.

#define NROWS 8192
#define DIM   256

__device__ __align__(16) int8_t g_q[NROWS * DIM];   // 2 MB quantized rows
__device__ __align__(16) float g_sc[NROWS];         // per-row dequant scale
__device__ float g_rowsum[NROWS];
__device__ float g_tdot[NROWS];

// smem layout (per CTA): A [0,32K), B0 [32K,64K), B1 [64K,96K)
#define SM_B0   32768u
#define SMEM_TOTAL 98304

// ---------------- helpers ----------------
__device__ __forceinline__ uint32_t smem_u32(const void* p) {
    uint32_t a;
    asm("{ .reg .u64 t; cvta.to.shared.u64 t, %1; cvt.u32.u64 %0, t; }"
        : "=r"(a) : "l"(p));
    return a;
}
__device__ __forceinline__ void cp16(uint32_t dst, const void* src) {
    asm volatile("cp.async.cg.shared.global [%0], [%1], 16;"
                 :: "r"(dst), "l"(src) : "memory");
}
__device__ __forceinline__ void ldsm_x4(uint32_t* r, uint32_t addr) {
    asm volatile("ldmatrix.sync.aligned.m8n8.x4.shared.b16 {%0,%1,%2,%3}, [%4];"
                 : "=r"(r[0]), "=r"(r[1]), "=r"(r[2]), "=r"(r[3]) : "r"(addr));
}
__device__ __forceinline__ void imma16832(int* c, const uint32_t* a,
                                          uint32_t b0, uint32_t b1) {
    asm volatile("mma.sync.aligned.m16n8k32.row.col.s32.s8.s8.s32 "
                 "{%0,%1,%2,%3}, {%4,%5,%6,%7}, {%8,%9}, {%0,%1,%2,%3};"
                 : "+r"(c[0]), "+r"(c[1]), "+r"(c[2]), "+r"(c[3])
                 : "r"(a[0]), "r"(a[1]), "r"(a[2]), "r"(a[3]), "r"(b0), "r"(b1));
}
__device__ __forceinline__ float fexp2(float x) {
    float e; asm("ex2.approx.ftz.f32 %0, %1;" : "=f"(e) : "f"(x)); return e;
}
__device__ __forceinline__ float flg2(float x) {
    float e; asm("lg2.approx.f32 %0, %1;" : "=f"(e) : "f"(x)); return e;
}

// ---------------------------------------------------------------------------
// Kernel 1: interleave + fp32 normalize + per-row int8 quantize.
// Also zeroes g_rowsum, g_tdot, and the output scalar.
// ---------------------------------------------------------------------------
__global__ void __launch_bounds__(256) normalize_kernel(
    const float* __restrict__ zis, const float* __restrict__ zjs,
    float* __restrict__ out) {
    int gtid = blockIdx.x * 256 + threadIdx.x;
    if (gtid < NROWS) { g_rowsum[gtid] = 0.f; g_tdot[gtid] = 0.f; }
    if (gtid == 0) out[0] = 0.f;

    int w = threadIdx.x >> 5, lid = threadIdx.x & 31;
    int row = blockIdx.x * 8 + w;
    const float* src = (row & 1) ? (zis + (size_t)(row >> 1) * DIM)
                                 : (zjs + (size_t)(row >> 1) * DIM);
    float4 v0 = *reinterpret_cast<const float4*>(src + lid * 4);
    float4 v1 = *reinterpret_cast<const float4*>(src + 128 + lid * 4);
    float s = v0.x*v0.x + v0.y*v0.y + v0.z*v0.z + v0.w*v0.w
            + v1.x*v1.x + v1.y*v1.y + v1.z*v1.z + v1.w*v1.w;
    float mx = fmaxf(fmaxf(fmaxf(fabsf(v0.x), fabsf(v0.y)),
                           fmaxf(fabsf(v0.z), fabsf(v0.w))),
                     fmaxf(fmaxf(fabsf(v1.x), fabsf(v1.y)),
                           fmaxf(fabsf(v1.z), fabsf(v1.w))));
    #pragma unroll
    for (int o = 16; o > 0; o >>= 1) {
        s  += __shfl_xor_sync(0xFFFFFFFF, s, o);
        mx  = fmaxf(mx, __shfl_xor_sync(0xFFFFFFFF, mx, o));
    }
    float inv = 1.0f / fmaxf(sqrtf(s), 1e-8f);
    float mxn = fmaxf(mx * inv, 1e-20f);
    if (lid == 0) g_sc[row] = mxn * (1.0f / 127.0f);

    float k = inv * (127.0f / mxn);
    int q0 = __float2int_rn(v0.x * k), q1 = __float2int_rn(v0.y * k);
    int q2 = __float2int_rn(v0.z * k), q3 = __float2int_rn(v0.w * k);
    int q4 = __float2int_rn(v1.x * k), q5 = __float2int_rn(v1.y * k);
    int q6 = __float2int_rn(v1.z * k), q7 = __float2int_rn(v1.w * k);
    uint32_t w0 = (q0 & 0xff) | ((q1 & 0xff) << 8)
                | ((q2 & 0xff) << 16) | ((q3 & 0xff) << 24);
    uint32_t w1 = (q4 & 0xff) | ((q5 & 0xff) << 8)
                | ((q6 & 0xff) << 16) | ((q7 & 0xff) << 24);
    uint32_t* dst = reinterpret_cast<uint32_t*>(g_q + (size_t)row * DIM);
    dst[lid]      = w0;
    dst[32 + lid] = w1;
}

// ---------------------------------------------------------------------------
// Kernel 2: persistent-band IMMA GEMM. 4 warps (2m x 2n), warp tile 64x64.
// grid (5, 32): 32 band-pairs (y, 63-y), 5 splits of the 65-tile list.
// ---------------------------------------------------------------------------
__global__ void __launch_bounds__(128, 2) gemm_kernel() {
    const int y  = blockIdx.y;         // pair id, 0..31
    const int kk = blockIdx.x;         // split, 0..4
    const int tlo = kk * 13, thi = tlo + 13;

    extern __shared__ __align__(16) char smem[];
    const uint32_t sb = smem_u32(smem);
    const int tid = threadIdx.x;
    const int lid = tid & 31;
    const int wid = tid >> 5;
    const int wm = wid >> 1;           // 0..1
    const int wn = wid & 1;            // 0..1
    const int lg = lid & 7;
    const int ltile = lid >> 3;
    const int trow8 = (ltile & 1) * 8;
    const int tk16 = (ltile >> 1) * 16;

    auto tband = [&](int t) { return (t < 64 - y) ? y : 63 - y; };
    auto tcol  = [&](int t) { return (t < 64 - y) ? y + t : t - 1; };

    // ---- loaders (g_q is 16B-aligned; offsets are multiples of 16) ----
    auto issue_A = [&](int band) {
        const char* src = (const char*)g_q + (size_t)band * 32768;
        #pragma unroll
        for (int it = 0; it < 16; it++) {
            int i = it * 128 + tid;
            int r = i >> 4, g = i & 15;
            cp16(sb + (uint32_t)(r * 256 + ((g * 16) ^ ((r & 7) << 4))),
                 src + (size_t)r * 256 + g * 16);
        }
    };
    auto issue_B = [&](int c, int s) {
        const char* src = (const char*)g_q + (size_t)c * 32768;
        uint32_t base = sb + SM_B0 + (uint32_t)s * 32768u;
        #pragma unroll
        for (int it = 0; it < 16; it++) {
            int i = it * 128 + tid;
            int r = i >> 4, g = i & 15;
            cp16(base + (uint32_t)(r * 256 + ((g * 16) ^ ((r & 7) << 4))),
                 src + (size_t)r * 256 + g * 16);
        }
    };

    const float C1 = 2.885390081777927f;   // 2*log2(e)

    int curband = tband(tlo);
    float rsV[4][2], rsC[4][2];            // row scales (raw and *C1)
    auto load_rsc = [&](int band) {
        #pragma unroll
        for (int mi = 0; mi < 4; mi++) {
            int r = band * 128 + wm * 64 + mi * 16 + (lid >> 2);
            rsV[mi][0] = g_sc[r];     rsC[mi][0] = rsV[mi][0] * C1;
            rsV[mi][1] = g_sc[r + 8]; rsC[mi][1] = rsV[mi][1] * C1;
        }
    };

    float rs[4][2];                        // register row exp-sums
    #pragma unroll
    for (int i = 0; i < 4; i++) { rs[i][0] = 0.f; rs[i][1] = 0.f; }

    auto emit_rows = [&](int band) {
        #pragma unroll
        for (int mi = 0; mi < 4; mi++) {
            #pragma unroll
            for (int h = 0; h < 2; h++) {
                float v = rs[mi][h];
                v += __shfl_xor_sync(0xFFFFFFFF, v, 1);
                v += __shfl_xor_sync(0xFFFFFFFF, v, 2);
                if ((lid & 3) == 0)
                    atomicAdd(&g_rowsum[band * 128 + wm * 64 + mi * 16
                                        + (lid >> 2) + h * 8], v);
                rs[mi][h] = 0.f;
            }
        }
    };

    // ---- prologue ----
    issue_A(curband);
    asm volatile("cp.async.commit_group;" ::: "memory");
    issue_B(tcol(tlo), tlo & 1);
    asm volatile("cp.async.commit_group;" ::: "memory");
    load_rsc(curband);

    int c_acc[4][8][4];

    for (int t = tlo; t < thi; t++) {
        const int bnd = tband(t), c = tcol(t);
        const int s = t & 1;
        const bool diag = (c == bnd);

        if (bnd != curband) {
            asm volatile("cp.async.wait_group 0;" ::: "memory");
            __syncthreads();                       // all done with old A/B
            emit_rows(curband);
            curband = bnd;
            load_rsc(curband);
            issue_A(curband);
            asm volatile("cp.async.commit_group;" ::: "memory");
            if (t + 1 < thi) {
                issue_B(tcol(t + 1), (t + 1) & 1);
                asm volatile("cp.async.commit_group;" ::: "memory");
                asm volatile("cp.async.wait_group 1;" ::: "memory");
            } else {
                asm volatile("cp.async.wait_group 0;" ::: "memory");
            }
            __syncthreads();
        } else {
            asm volatile("cp.async.wait_group 0;" ::: "memory");
            __syncthreads();
            if (t + 1 < thi) {
                issue_B(tcol(t + 1), (t + 1) & 1);
                asm volatile("cp.async.commit_group;" ::: "memory");
            }
        }

        // column scales for this tile -> registers (L1/L2 hits; overlaps MMA)
        float2 cscr[8];
        #pragma unroll
        for (int ni = 0; ni < 8; ni++)
            cscr[ni] = ((const float2*)g_sc)[c * 64 + wn * 32 + ni * 4 + (lid & 3)];

        // ---- compute 128x128x256 (A resident, B stage s) ----
        #pragma unroll
        for (int mi = 0; mi < 4; mi++)
            #pragma unroll
            for (int ni = 0; ni < 8; ni++)
                #pragma unroll
                for (int q = 0; q < 4; q++) c_acc[mi][ni][q] = 0;

        const uint32_t bsb = sb + SM_B0 + (uint32_t)s * 32768u;
        #pragma unroll
        for (int k32 = 0; k32 < 8; k32++) {
            const int kb = k32 * 32 + tk16;
            uint32_t a[4][4], bb[4][4];
            #pragma unroll
            for (int mi = 0; mi < 4; mi++) {
                int m = wm * 64 + mi * 16 + trow8 + lg;
                ldsm_x4(a[mi], sb + (uint32_t)(m * 256 + (kb ^ ((m & 7) << 4))));
            }
            #pragma unroll
            for (int nb = 0; nb < 4; nb++) {
                int n = wn * 64 + nb * 16 + trow8 + lg;
                ldsm_x4(bb[nb], bsb + (uint32_t)(n * 256 + (kb ^ ((n & 7) << 4))));
            }
            #pragma unroll
            for (int mi = 0; mi < 4; mi++) {
                #pragma unroll
                for (int ni = 0; ni < 8; ni++) {
                    const uint32_t* B = bb[ni >> 1];
                    uint32_t b0 = (ni & 1) ? B[1] : B[0];
                    uint32_t b1 = (ni & 1) ? B[3] : B[2];
                    imma16832(c_acc[mi][ni], a[mi], b0, b1);
                }
            }
        }

        // ---- epilogue (registers only) ----
        float cs[8][2];
        #pragma unroll
        for (int i = 0; i < 8; i++) { cs[i][0] = 0.f; cs[i][1] = 0.f; }

        #pragma unroll
        for (int mi = 0; mi < 4; mi++) {
            #pragma unroll
            for (int ni = 0; ni < 8; ni++) {
                float2 cp = cscr[ni];
                float df0 = (float)c_acc[mi][ni][0];
                float df1 = (float)c_acc[mi][ni][1];
                float df2 = (float)c_acc[mi][ni][2];
                float df3 = (float)c_acc[mi][ni][3];
                float e0 = fexp2(fmaf(df0 * rsC[mi][0], cp.x, -C1));
                float e1 = fexp2(fmaf(df1 * rsC[mi][0], cp.y, -C1));
                float e2 = fexp2(fmaf(df2 * rsC[mi][1], cp.x, -C1));
                float e3 = fexp2(fmaf(df3 * rsC[mi][1], cp.y, -C1));
                if (diag) {
                    int r0 = curband * 128 + wm * 64 + mi * 16 + (lid >> 2);
                    int r1 = r0 + 8;
                    int cb = c * 128 + wn * 64 + ni * 8 + (lid & 3) * 2;
                    if (cb     == r0) e0 = 0.f;
                    if (cb + 1 == r0) e1 = 0.f;
                    if (cb     == r1) e2 = 0.f;
                    if (cb + 1 == r1) e3 = 0.f;
                    if (cb     == (r0 ^ 1)) g_tdot[r0] = df0 * rsV[mi][0] * cp.x;
                    if (cb + 1 == (r0 ^ 1)) g_tdot[r0] = df1 * rsV[mi][0] * cp.y;
                    if (cb     == (r1 ^ 1)) g_tdot[r1] = df2 * rsV[mi][1] * cp.x;
                    if (cb + 1 == (r1 ^ 1)) g_tdot[r1] = df3 * rsV[mi][1] * cp.y;
                }
                rs[mi][0] += e0 + e1;
                rs[mi][1] += e2 + e3;
                cs[ni][0] += e0 + e2;
                cs[ni][1] += e1 + e3;
            }
        }
        if (!diag) {   // col sums -> global RED (diag tiles hold both orders)
            #pragma unroll
            for (int ni = 0; ni < 8; ni++) {
                #pragma unroll
                for (int h = 0; h < 2; h++) {
                    cs[ni][h] += __shfl_xor_sync(0xFFFFFFFF, cs[ni][h], 4);
                    cs[ni][h] += __shfl_xor_sync(0xFFFFFFFF, cs[ni][h], 8);
                    cs[ni][h] += __shfl_xor_sync(0xFFFFFFFF, cs[ni][h], 16);
                }
            }
            if (lid < 4) {
                #pragma unroll
                for (int ni = 0; ni < 8; ni++) {
                    int cb = c * 128 + wn * 64 + ni * 8 + lid * 2;
                    atomicAdd(&g_rowsum[cb],     cs[ni][0]);
                    atomicAdd(&g_rowsum[cb + 1], cs[ni][1]);
                }
            }
        }
    }
    emit_rows(curband);
}

// ---------------------------------------------------------------------------
// Kernel 3: final reduction -> mean loss (32 blocks, atomic combine).
// ---------------------------------------------------------------------------
__global__ void __launch_bounds__(256) finalize_kernel(float* __restrict__ out) {
    int r = blockIdx.x * 256 + threadIdx.x;
    const float LN2 = 0.6931471805599453f;
    float acc = 2.f + LN2 * flg2(g_rowsum[r]) - 2.f * g_tdot[r];
    #pragma unroll
    for (int o = 16; o > 0; o >>= 1) acc += __shfl_xor_sync(0xFFFFFFFF, acc, o);
    __shared__ float sh[8];
    int w = threadIdx.x >> 5, l = threadIdx.x & 31;
    if (l == 0) sh[w] = acc;
    __syncthreads();
    if (threadIdx.x < 8) {
        float v = sh[threadIdx.x];
        v += __shfl_xor_sync(0xFF, v, 1);
        v += __shfl_xor_sync(0xFF, v, 2);
        v += __shfl_xor_sync(0xFF, v, 4);
        if (threadIdx.x == 0) atomicAdd(out, v * (1.0f / (float)NROWS));
    }
}

// ---------------------------------------------------------------------------
extern "C" void kernel_launch(void* const* d_in, const int* in_sizes, int n_in,
                              void* d_out, int out_size) {
    const float* zis = (const float*)d_in[0];
    const float* zjs = (const float*)d_in[1];
    float* out = (float*)d_out;

    cudaFuncSetAttribute(gemm_kernel,
                         cudaFuncAttributeMaxDynamicSharedMemorySize, SMEM_TOTAL);

    normalize_kernel<<<NROWS / 8, 256>>>(zis, zjs, out);
    dim3 grid(5, 32);
    gemm_kernel<<<grid, 128, SMEM_TOTAL>>>();
    finalize_kernel<<<NROWS / 256, 256>>>(out);
}

// round 9
// speedup vs baseline: 1.4769x; 1.4769x over previous
#include <cuda_runtime.h>
#include <math.h>
#include <stdint.h>

// NT-Xent loss. N=8192 rows (interleaved zjs/zis), D=256.
// score = 2*cos(i,j) in [-2,2] -> fixed-shift logsumexp:
//   loss_i = 2 + ln(sum_{j!=i} exp(2 d_ij - 2)) - 2 d_{i, i^1}
// Symmetric int8 IMMA GEMM, exact triangular grid (2080 CTAs, 256 thr,
// 8 warps 64x32, 2 CTAs/SM). Epilogue reduces via shfl + direct global RED.

#define NROWS 8192
#define DIM   256

__device__ __align__(16) int8_t g_q[NROWS * DIM];   // 2 MB quantized rows
__device__ __align__(16) float g_sc[NROWS];         // per-row dequant scale
__device__ float g_rowsum[NROWS];
__device__ float g_tdot[NROWS];

// ---------------- helpers ----------------
__device__ __forceinline__ uint32_t smem_u32(const void* p) {
    uint32_t a;
    asm("{ .reg .u64 t; cvta.to.shared.u64 t, %1; cvt.u32.u64 %0, t; }"
        : "=r"(a) : "l"(p));
    return a;
}
__device__ __forceinline__ void cp16(uint32_t dst, const void* src) {
    asm volatile("cp.async.cg.shared.global [%0], [%1], 16;"
                 :: "r"(dst), "l"(src) : "memory");
}
__device__ __forceinline__ void ldsm_x4(uint32_t* r, uint32_t addr) {
    asm volatile("ldmatrix.sync.aligned.m8n8.x4.shared.b16 {%0,%1,%2,%3}, [%4];"
                 : "=r"(r[0]), "=r"(r[1]), "=r"(r[2]), "=r"(r[3]) : "r"(addr));
}
__device__ __forceinline__ void imma16832(int* c, const uint32_t* a,
                                          uint32_t b0, uint32_t b1) {
    asm volatile("mma.sync.aligned.m16n8k32.row.col.s32.s8.s8.s32 "
                 "{%0,%1,%2,%3}, {%4,%5,%6,%7}, {%8,%9}, {%0,%1,%2,%3};"
                 : "+r"(c[0]), "+r"(c[1]), "+r"(c[2]), "+r"(c[3])
                 : "r"(a[0]), "r"(a[1]), "r"(a[2]), "r"(a[3]), "r"(b0), "r"(b1));
}
__device__ __forceinline__ float fexp2(float x) {
    float e; asm("ex2.approx.ftz.f32 %0, %1;" : "=f"(e) : "f"(x)); return e;
}
__device__ __forceinline__ float flg2(float x) {
    float e; asm("lg2.approx.f32 %0, %1;" : "=f"(e) : "f"(x)); return e;
}

// ---------------------------------------------------------------------------
// Kernel 1: interleave + fp32 normalize + per-row int8 quantize.
// Also zeroes g_rowsum, g_tdot, and the output scalar.
// ---------------------------------------------------------------------------
__global__ void __launch_bounds__(256) normalize_kernel(
    const float* __restrict__ zis, const float* __restrict__ zjs,
    float* __restrict__ out) {
    int gtid = blockIdx.x * 256 + threadIdx.x;
    if (gtid < NROWS) { g_rowsum[gtid] = 0.f; g_tdot[gtid] = 0.f; }
    if (gtid == 0) out[0] = 0.f;

    int w = threadIdx.x >> 5, lid = threadIdx.x & 31;
    int row = blockIdx.x * 8 + w;
    const float* src = (row & 1) ? (zis + (size_t)(row >> 1) * DIM)
                                 : (zjs + (size_t)(row >> 1) * DIM);
    float4 v0 = *reinterpret_cast<const float4*>(src + lid * 4);
    float4 v1 = *reinterpret_cast<const float4*>(src + 128 + lid * 4);
    float s = v0.x*v0.x + v0.y*v0.y + v0.z*v0.z + v0.w*v0.w
            + v1.x*v1.x + v1.y*v1.y + v1.z*v1.z + v1.w*v1.w;
    float mx = fmaxf(fmaxf(fmaxf(fabsf(v0.x), fabsf(v0.y)),
                           fmaxf(fabsf(v0.z), fabsf(v0.w))),
                     fmaxf(fmaxf(fabsf(v1.x), fabsf(v1.y)),
                           fmaxf(fabsf(v1.z), fabsf(v1.w))));
    #pragma unroll
    for (int o = 16; o > 0; o >>= 1) {
        s  += __shfl_xor_sync(0xFFFFFFFF, s, o);
        mx  = fmaxf(mx, __shfl_xor_sync(0xFFFFFFFF, mx, o));
    }
    float inv = 1.0f / fmaxf(sqrtf(s), 1e-8f);
    float mxn = fmaxf(mx * inv, 1e-20f);
    if (lid == 0) g_sc[row] = mxn * (1.0f / 127.0f);

    float k = inv * (127.0f / mxn);
    int q0 = __float2int_rn(v0.x * k), q1 = __float2int_rn(v0.y * k);
    int q2 = __float2int_rn(v0.z * k), q3 = __float2int_rn(v0.w * k);
    int q4 = __float2int_rn(v1.x * k), q5 = __float2int_rn(v1.y * k);
    int q6 = __float2int_rn(v1.z * k), q7 = __float2int_rn(v1.w * k);
    uint32_t w0 = (q0 & 0xff) | ((q1 & 0xff) << 8)
                | ((q2 & 0xff) << 16) | ((q3 & 0xff) << 24);
    uint32_t w1 = (q4 & 0xff) | ((q5 & 0xff) << 8)
                | ((q6 & 0xff) << 16) | ((q7 & 0xff) << 24);
    uint32_t* dst = reinterpret_cast<uint32_t*>(g_q + (size_t)row * DIM);
    dst[lid]      = w0;
    dst[32 + lid] = w1;
}

// ---------------------------------------------------------------------------
// Kernel 2: upper-triangle 128x128 int8 IMMA tiles + symmetric epilogue.
// grid (65, 32) packs the 2080-tile triangle exactly.
// 8 warps (2m x 4n), warp tile 64x32. 2-stage smem (64 KB) + scales (1 KB).
// ---------------------------------------------------------------------------
#define SM_SCALES 65536u
#define SMEM_TOTAL 66560

__global__ void __launch_bounds__(256, 2) gemm_kernel() {
    // triangular decode: pair row y (len 64-y) with row 63-y (len y+1)
    const int x = blockIdx.x, y = blockIdx.y;
    int by, bx;
    if (x < 64 - y) { by = y;      bx = y + x; }
    else            { by = 63 - y; bx = x - 1; }
    const bool diag = (bx == by);

    extern __shared__ __align__(16) char smem[];
    const uint32_t sb = smem_u32(smem);
    const int tid = threadIdx.x;
    const int lid = tid & 31;
    const int wid = tid >> 5;
    const int wm = wid >> 2;
    const int wn = wid & 3;
    const int wrow = wm * 64;
    const int wcol = wn * 32;
    const int row0 = by * 128;
    const int col0 = bx * 128;

    int c[4][4][4];
    #pragma unroll
    for (int mi = 0; mi < 4; mi++)
        #pragma unroll
        for (int ni = 0; ni < 4; ni++)
            #pragma unroll
            for (int q = 0; q < 4; q++) c[mi][ni][q] = 0;

    const char* gA = (const char*)g_q + (size_t)row0 * 256;
    const char* gB = (const char*)g_q + (size_t)col0 * 256;

    // scales into smem (row[128] then col[128] floats)
    if (tid < 128) {
        ((float*)(smem + SM_SCALES))[tid]       = g_sc[row0 + tid];
        ((float*)(smem + SM_SCALES))[128 + tid] = g_sc[col0 + tid];
    }

    // ---- stage loader: K-half ch (128 B of each row) into stage s (32 KB) ----
    auto load_stage = [&](int ch, int s) {
        uint32_t dA = sb + (uint32_t)s * 32768u;
        const char* srcA = gA + ch * 128;
        #pragma unroll
        for (int it = 0; it < 4; it++) {
            int i = it * 256 + tid;          // 0..1023
            int r = i >> 3, g = i & 7;
            uint32_t off = (uint32_t)(r * 128 + ((g * 16) ^ ((r & 7) << 4)));
            cp16(dA + off, srcA + (size_t)r * 256 + g * 16);
        }
        if (!diag) {
            uint32_t dB = dA + 16384u;
            const char* srcB = gB + ch * 128;
            #pragma unroll
            for (int it = 0; it < 4; it++) {
                int i = it * 256 + tid;
                int r = i >> 3, g = i & 7;
                uint32_t off = (uint32_t)(r * 128 + ((g * 16) ^ ((r & 7) << 4)));
                cp16(dB + off, srcB + (size_t)r * 256 + g * 16);
            }
        }
        asm volatile("cp.async.commit_group;" ::: "memory");
    };

    const int lg = lid & 7;
    const int ltile = lid >> 3;
    const int trow8 = (ltile & 1) * 8;
    const int tk16 = (ltile >> 1) * 16;

    auto compute = [&](int s) {
        uint32_t asb = sb + (uint32_t)s * 32768u;
        uint32_t bsb = diag ? asb : (asb + 16384u);
        #pragma unroll
        for (int k32 = 0; k32 < 4; k32++) {
            int kb = k32 * 32 + tk16;
            uint32_t a[4][4], bb[2][4];
            #pragma unroll
            for (int mi = 0; mi < 4; mi++) {
                int m = wrow + mi * 16 + trow8 + lg;
                ldsm_x4(a[mi], asb + (uint32_t)(m * 128 + (kb ^ ((m & 7) << 4))));
            }
            #pragma unroll
            for (int nb = 0; nb < 2; nb++) {
                int n = wcol + nb * 16 + trow8 + lg;
                ldsm_x4(bb[nb], bsb + (uint32_t)(n * 128 + (kb ^ ((n & 7) << 4))));
            }
            #pragma unroll
            for (int mi = 0; mi < 4; mi++) {
                #pragma unroll
                for (int ni = 0; ni < 4; ni++) {
                    const uint32_t* B = bb[ni >> 1];
                    uint32_t b0 = (ni & 1) ? B[1] : B[0];
                    uint32_t b1 = (ni & 1) ? B[3] : B[2];
                    imma16832(c[mi][ni], a[mi], b0, b1);
                }
            }
        }
    };

    // ---- two K-halves, 2-stage pipeline ----
    load_stage(0, 0);
    load_stage(1, 1);
    asm volatile("cp.async.wait_group 1;" ::: "memory");
    __syncthreads();
    compute(0);
    asm volatile("cp.async.wait_group 0;" ::: "memory");
    __syncthreads();
    compute(1);

    // ---- epilogue: dequant + shifted exp-sum; reductions -> global RED ----
    const float C1 = 2.885390081777927f;   // 2*log2(e)
    const float* rsc = (const float*)(smem + SM_SCALES);
    const float* csc = rsc + 128;

    float rs[4][2], cs[4][2];
    #pragma unroll
    for (int i = 0; i < 4; i++) { rs[i][0]=rs[i][1]=0.f; cs[i][0]=cs[i][1]=0.f; }

    #pragma unroll
    for (int mi = 0; mi < 4; mi++) {
        int rl0 = wrow + mi * 16 + (lid >> 2);
        int rl1 = rl0 + 8;
        int r0 = row0 + rl0, r1 = row0 + rl1;
        float s0 = rsc[rl0] * C1, s1 = rsc[rl1] * C1;
        #pragma unroll
        for (int ni = 0; ni < 4; ni++) {
            int cl = wcol + ni * 8 + (lid & 3) * 2;
            int cb = col0 + cl;
            float sc0 = csc[cl], sc1 = csc[cl + 1];
            float d0 = (float)c[mi][ni][0] * (s0 * sc0);
            float d1 = (float)c[mi][ni][1] * (s0 * sc1);
            float d2 = (float)c[mi][ni][2] * (s1 * sc0);
            float d3 = (float)c[mi][ni][3] * (s1 * sc1);
            float e0 = fexp2(d0 - C1);
            float e1 = fexp2(d1 - C1);
            float e2 = fexp2(d2 - C1);
            float e3 = fexp2(d3 - C1);
            if (diag) {
                const float IC1 = 0.34657359027997264f;  // 1/C1 * ... (=ln2/2)
                if (cb     == r0) e0 = 0.f;
                if (cb + 1 == r0) e1 = 0.f;
                if (cb     == r1) e2 = 0.f;
                if (cb + 1 == r1) e3 = 0.f;
                if (cb     == (r0 ^ 1)) g_tdot[r0] = d0 * IC1;
                if (cb + 1 == (r0 ^ 1)) g_tdot[r0] = d1 * IC1;
                if (cb     == (r1 ^ 1)) g_tdot[r1] = d2 * IC1;
                if (cb + 1 == (r1 ^ 1)) g_tdot[r1] = d3 * IC1;
            }
            rs[mi][0] += e0 + e1;
            rs[mi][1] += e2 + e3;
            cs[ni][0] += e0 + e2;
            cs[ni][1] += e1 + e3;
        }
    }

    // rows: shfl-reduce across the 4 lanes sharing each row -> global RED
    #pragma unroll
    for (int mi = 0; mi < 4; mi++) {
        #pragma unroll
        for (int h = 0; h < 2; h++) {
            float v = rs[mi][h];
            v += __shfl_xor_sync(0xFFFFFFFF, v, 1);
            v += __shfl_xor_sync(0xFFFFFFFF, v, 2);
            if ((lid & 3) == 0)
                atomicAdd(&g_rowsum[row0 + wrow + mi * 16 + (lid >> 2) + h * 8], v);
        }
    }
    // cols (offdiag only): shfl-reduce across 8 lanes -> global RED
    if (!diag) {
        #pragma unroll
        for (int ni = 0; ni < 4; ni++) {
            #pragma unroll
            for (int h = 0; h < 2; h++) {
                float v = cs[ni][h];
                v += __shfl_xor_sync(0xFFFFFFFF, v, 4);
                v += __shfl_xor_sync(0xFFFFFFFF, v, 8);
                v += __shfl_xor_sync(0xFFFFFFFF, v, 16);
                if (lid < 4)
                    atomicAdd(&g_rowsum[col0 + wcol + ni * 8 + lid * 2 + h], v);
            }
        }
    }
}

// ---------------------------------------------------------------------------
// Kernel 3: final reduction -> mean loss (32 blocks, atomic combine).
// tdot stored as cosine dot; score contribution = 2*tdot.
// ---------------------------------------------------------------------------
__global__ void __launch_bounds__(256) finalize_kernel(float* __restrict__ out) {
    int r = blockIdx.x * 256 + threadIdx.x;
    const float LN2 = 0.6931471805599453f;
    float acc = 2.f + LN2 * flg2(g_rowsum[r]) - 2.f * g_tdot[r];
    #pragma unroll
    for (int o = 16; o > 0; o >>= 1) acc += __shfl_xor_sync(0xFFFFFFFF, acc, o);
    __shared__ float sh[8];
    int w = threadIdx.x >> 5, l = threadIdx.x & 31;
    if (l == 0) sh[w] = acc;
    __syncthreads();
    if (threadIdx.x < 8) {
        float v = sh[threadIdx.x];
        v += __shfl_xor_sync(0xFF, v, 1);
        v += __shfl_xor_sync(0xFF, v, 2);
        v += __shfl_xor_sync(0xFF, v, 4);
        if (threadIdx.x == 0) atomicAdd(out, v * (1.0f / (float)NROWS));
    }
}

// ---------------------------------------------------------------------------
extern "C" void kernel_launch(void* const* d_in, const int* in_sizes, int n_in,
                              void* d_out, int out_size) {
    const float* zis = (const float*)d_in[0];
    const float* zjs = (const float*)d_in[1];
    float* out = (float*)d_out;

    cudaFuncSetAttribute(gemm_kernel,
                         cudaFuncAttributeMaxDynamicSharedMemorySize, SMEM_TOTAL);

    normalize_kernel<<<NROWS / 8, 256>>>(zis, zjs, out);
    dim3 grid(65, 32);
    gemm_kernel<<<grid, 256, SMEM_TOTAL>>>();
    finalize_kernel<<<NROWS / 256, 256>>>(out);
}